// round 2
// baseline (speedup 1.0000x reference)
#include <cuda_runtime.h>

#define NNODES 100000
#define NEDGES 3200000
#define DIN 64
#define DE 16
#define HID 16

// Scratch (device globals: no allocation allowed in kernel_launch)
__device__ __align__(256) float g_p1[NNODES * HID];     // x@W1x + b_msg1
__device__ __align__(256) float g_s1[NNODES * HID];     // x@W_skip1 + b_skip1
__device__ __align__(256) float g_acc1[NNODES * 32];    // [0:16) sum p1[src], [16:32) sum e
__device__ __align__(256) float g_p2[NNODES * HID];     // h@W2x + b_msg2
__device__ __align__(256) float g_s2[NNODES * HID];     // h@W_skip2 + b_skip2
__device__ __align__(256) float g_acc2[NNODES * HID];   // sum p2[src]

__device__ __forceinline__ void red_v4(float* addr, float4 v) {
    asm volatile("red.global.add.v4.f32 [%0], {%1,%2,%3,%4};"
                 :: "l"(addr), "f"(v.x), "f"(v.y), "f"(v.z), "f"(v.w)
                 : "memory");
}

// ---------------------------------------------------------------------------
// K0: zero the accumulators (19.2 MB)
// ---------------------------------------------------------------------------
__global__ __launch_bounds__(256) void k_zero() {
    int i = blockIdx.x * blockDim.x + threadIdx.x;
    float4 z = make_float4(0.f, 0.f, 0.f, 0.f);
    const int n1 = NNODES * 8;   // g_acc1 as float4
    const int n2 = NNODES * 4;   // g_acc2 as float4
    if (i < n1)            reinterpret_cast<float4*>(g_acc1)[i] = z;
    else if (i < n1 + n2)  reinterpret_cast<float4*>(g_acc2)[i - n1] = z;
}

// ---------------------------------------------------------------------------
// K1: per-node p1 = x@W1x + b_msg1 ; s1 = x@W_skip1 + b_skip1
// 16 threads per node, block = 16 nodes. x staged via shared (coalesced).
// ---------------------------------------------------------------------------
__global__ __launch_bounds__(256) void k_node1(
    const float* __restrict__ x,
    const float* __restrict__ Wm1, const float* __restrict__ bm1,
    const float* __restrict__ Ws1, const float* __restrict__ bs1)
{
    __shared__ float sWx[DIN * HID];   // W_msg1 rows 0..63
    __shared__ float sWs[DIN * HID];   // W_skip1
    __shared__ float sx[16][DIN];
    int t = threadIdx.x;
    for (int i = t; i < DIN * HID; i += 256) { sWx[i] = Wm1[i]; sWs[i] = Ws1[i]; }
    int ln = t >> 4, j = t & 15;
    int v = blockIdx.x * 16 + ln;
    if (v < NNODES) {
        // 16 threads x float4 = 64 floats of node v
        reinterpret_cast<float4*>(sx[ln])[j] =
            reinterpret_cast<const float4*>(x + (size_t)v * DIN)[j];
    }
    __syncthreads();
    if (v >= NNODES) return;
    float ap = bm1[j], as = bs1[j];
    #pragma unroll
    for (int k = 0; k < DIN; k++) {
        float xv = sx[ln][k];
        ap = fmaf(xv, sWx[k * HID + j], ap);
        as = fmaf(xv, sWs[k * HID + j], as);
    }
    g_p1[(size_t)v * HID + j] = ap;
    g_s1[(size_t)v * HID + j] = as;
}

// ---------------------------------------------------------------------------
// K2: edge pass 1 — 4 threads per edge, each owns one float4 chunk.
//   acc1[dst][c]      += p1[src][c]      (p-part)
//   acc1[dst][16 + c] += edge_attr[e][c] (e-part; scattered ONCE, reused by both convs)
// ---------------------------------------------------------------------------
__global__ __launch_bounds__(256) void k_edge1(
    const int* __restrict__ src, const int* __restrict__ dst,
    const float* __restrict__ ea)
{
    int tid = blockIdx.x * blockDim.x + threadIdx.x;
    if (tid >= NEDGES * 4) return;
    int i = tid >> 2, c = tid & 3;
    int s = __ldg(src + i);
    int d = __ldg(dst + i);
    // ea element (i*16 + c*4) as float4 == linear float4 index tid (coalesced)
    float4 e = reinterpret_cast<const float4*>(ea)[tid];
    float4 q = __ldg(reinterpret_cast<const float4*>(g_p1 + (size_t)s * HID + c * 4));
    red_v4(g_acc1 + (size_t)d * 32 + c * 4, q);
    red_v4(g_acc1 + (size_t)d * 32 + 16 + c * 4, e);
}

// ---------------------------------------------------------------------------
// K3: per-node conv1 epilogue + conv2 prologue (one thread per node)
//   h  = relu(accP1 + Ae@We1 + s1)
//   p2 = h@W2x + b_msg2 ; s2 = h@W_skip2 + b_skip2
// ---------------------------------------------------------------------------
__global__ __launch_bounds__(256) void k_node2(
    const float* __restrict__ Wm1,
    const float* __restrict__ Wm2, const float* __restrict__ bm2,
    const float* __restrict__ Ws2, const float* __restrict__ bs2)
{
    __shared__ float sWe1[HID * HID];  // W_msg1 rows 64..79
    __shared__ float sW2x[HID * HID];  // W_msg2 rows 0..15
    __shared__ float sWs2[HID * HID];  // W_skip2
    __shared__ float sb2[HID], sbs2[HID];
    int t = threadIdx.x;
    if (t < 256) { sWe1[t] = Wm1[DIN * HID + t]; sW2x[t] = Wm2[t]; sWs2[t] = Ws2[t]; }
    if (t < HID) { sb2[t] = bm2[t]; sbs2[t] = bs2[t]; }
    __syncthreads();
    int v = blockIdx.x * blockDim.x + t;
    if (v >= NNODES) return;

    float accp[16], acce[16], s1v[16];
    const float4* r = reinterpret_cast<const float4*>(g_acc1 + (size_t)v * 32);
    #pragma unroll
    for (int q = 0; q < 4; q++) {
        float4 a = r[q], b = r[q + 4];
        accp[q*4+0]=a.x; accp[q*4+1]=a.y; accp[q*4+2]=a.z; accp[q*4+3]=a.w;
        acce[q*4+0]=b.x; acce[q*4+1]=b.y; acce[q*4+2]=b.z; acce[q*4+3]=b.w;
    }
    const float4* rs = reinterpret_cast<const float4*>(g_s1 + (size_t)v * HID);
    #pragma unroll
    for (int q = 0; q < 4; q++) {
        float4 a = rs[q];
        s1v[q*4+0]=a.x; s1v[q*4+1]=a.y; s1v[q*4+2]=a.z; s1v[q*4+3]=a.w;
    }

    float h[16];
    #pragma unroll
    for (int j = 0; j < HID; j++) {
        float hv = accp[j] + s1v[j];
        #pragma unroll
        for (int k = 0; k < HID; k++) hv = fmaf(acce[k], sWe1[k * HID + j], hv);
        h[j] = fmaxf(hv, 0.f);
    }
    #pragma unroll
    for (int j = 0; j < HID; j++) {
        float pv = sb2[j], sv = sbs2[j];
        #pragma unroll
        for (int k = 0; k < HID; k++) {
            pv = fmaf(h[k], sW2x[k * HID + j], pv);
            sv = fmaf(h[k], sWs2[k * HID + j], sv);
        }
        g_p2[(size_t)v * HID + j] = pv;
        g_s2[(size_t)v * HID + j] = sv;
    }
}

// ---------------------------------------------------------------------------
// K4: edge pass 2 — acc2[dst] += p2[src]  (4 threads/edge)
// ---------------------------------------------------------------------------
__global__ __launch_bounds__(256) void k_edge2(
    const int* __restrict__ src, const int* __restrict__ dst)
{
    int tid = blockIdx.x * blockDim.x + threadIdx.x;
    if (tid >= NEDGES * 4) return;
    int i = tid >> 2, c = tid & 3;
    int s = __ldg(src + i);
    int d = __ldg(dst + i);
    float4 q = __ldg(reinterpret_cast<const float4*>(g_p2 + (size_t)s * HID + c * 4));
    red_v4(g_acc2 + (size_t)d * HID + c * 4, q);
}

// ---------------------------------------------------------------------------
// K5: final epilogue (16 threads per node)
//   h2 = acc2 + Ae@We2 + s2 ; out = h2@W_lin3 + b_lin3
// ---------------------------------------------------------------------------
__global__ __launch_bounds__(256) void k_node3(
    const float* __restrict__ Wm2,
    const float* __restrict__ Wl3, const float* __restrict__ bl3,
    float* __restrict__ out)
{
    __shared__ float sWe2[HID * HID];   // W_msg2 rows 16..31
    __shared__ float sWl[HID * DIN];    // W_lin3 (16x64)
    __shared__ float sbl[DIN];
    __shared__ float sh2[16][HID];
    int t = threadIdx.x;
    for (int i = t; i < HID * DIN; i += 256) sWl[i] = Wl3[i];
    if (t < 256) sWe2[t] = Wm2[HID * HID + t];
    if (t < DIN) sbl[t] = bl3[t];
    __syncthreads();

    int ln = t >> 4, j = t & 15;
    int v = blockIdx.x * 16 + ln;
    float val = 0.f;
    if (v < NNODES) {
        val = g_acc2[(size_t)v * HID + j] + g_s2[(size_t)v * HID + j];
        const float* acce = g_acc1 + (size_t)v * 32 + 16;
        #pragma unroll
        for (int k = 0; k < HID; k++) val = fmaf(acce[k], sWe2[k * HID + j], val);
    }
    sh2[ln][j] = val;
    __syncthreads();
    if (v >= NNODES) return;

    float o0 = sbl[j*4+0], o1 = sbl[j*4+1], o2 = sbl[j*4+2], o3 = sbl[j*4+3];
    #pragma unroll
    for (int k = 0; k < HID; k++) {
        float hk = sh2[ln][k];
        const float* w = sWl + k * DIN + j * 4;
        o0 = fmaf(hk, w[0], o0);
        o1 = fmaf(hk, w[1], o1);
        o2 = fmaf(hk, w[2], o2);
        o3 = fmaf(hk, w[3], o3);
    }
    reinterpret_cast<float4*>(out + (size_t)v * DIN)[j] = make_float4(o0, o1, o2, o3);
}

// ---------------------------------------------------------------------------
extern "C" void kernel_launch(void* const* d_in, const int* in_sizes, int n_in,
                              void* d_out, int out_size)
{
    const float* x   = (const float*)d_in[0];
    const int*   ei  = (const int*)  d_in[1];
    const float* ea  = (const float*)d_in[2];
    const float* Wm1 = (const float*)d_in[3];
    const float* bm1 = (const float*)d_in[4];
    const float* Ws1 = (const float*)d_in[5];
    const float* bs1 = (const float*)d_in[6];
    const float* Wm2 = (const float*)d_in[7];
    const float* bm2 = (const float*)d_in[8];
    const float* Ws2 = (const float*)d_in[9];
    const float* bs2 = (const float*)d_in[10];
    const float* Wl3 = (const float*)d_in[11];
    const float* bl3 = (const float*)d_in[12];
    const int* src = ei;
    const int* dst = ei + NEDGES;
    float* out = (float*)d_out;

    k_zero <<<(NNODES * 12 + 255) / 256, 256>>>();
    k_node1<<<(NNODES + 15) / 16,        256>>>(x, Wm1, bm1, Ws1, bs1);
    k_edge1<<<(NEDGES * 4 + 255) / 256,  256>>>(src, dst, ea);
    k_node2<<<(NNODES + 255) / 256,      256>>>(Wm1, Wm2, bm2, Ws2, bs2);
    k_edge2<<<(NEDGES * 4 + 255) / 256,  256>>>(src, dst);
    k_node3<<<(NNODES + 15) / 16,        256>>>(Wm2, Wl3, bl3, out);
}